// round 16
// baseline (speedup 1.0000x reference)
// v15 — GEMM2 to 3 CTAs/SM: <NB=1, S=3, MW=4, TN=64, OCC=3>.
#include <cuda_runtime.h>
#include <cuda_bf16.h>
#include <cstdint>
#include <cstddef>

#define TOKENS 16384
#define DDIM   2048
#define IDIM   5632
#define NGATE  (2*IDIM)

// ------------------------------------------------------------------
// Device-global scratch (module-load allocation; no runtime allocs)
// ------------------------------------------------------------------
__device__ int8_t g_xq1[(size_t)TOKENS * DDIM];   // quantized x (int8 codes)
__device__ float  g_isx1[TOKENS];                 // per-token dequant scale (absmax/127)
__device__ int8_t g_wqg[(size_t)NGATE * DDIM];    // ternary w_gate (int8)
__device__ int8_t g_wqd[(size_t)DDIM * IDIM];     // ternary w_down (int8)
__device__ float  g_swi[(size_t)TOKENS * IDIM];   // swiglu intermediate (fp32)
__device__ int8_t g_xq2[(size_t)TOKENS * IDIM];   // quantized swiglu (int8 codes)
__device__ float  g_isx2[TOKENS];
__device__ double g_part[1024];                   // reduction partials
__device__ float  g_wdq[2];                       // weight dequant factors (mean)

// ------------------------------------------------------------------
// PTX helpers (sm_100-baseline: cp.async / ldmatrix / mma.sync s8)
// ------------------------------------------------------------------
__device__ __forceinline__ uint32_t smem_u32(const void* p) {
    uint32_t a;
    asm("{ .reg .u64 t; cvta.to.shared.u64 t, %1; cvt.u32.u64 %0, t; }" : "=r"(a) : "l"(p));
    return a;
}
__device__ __forceinline__ void cp16(uint32_t dst, const void* src) {
    asm volatile("cp.async.cg.shared.global [%0], [%1], 16;" :: "r"(dst), "l"(src) : "memory");
}
__device__ __forceinline__ void cp_commit() {
    asm volatile("cp.async.commit_group;" ::: "memory");
}
template<int N> __device__ __forceinline__ void cp_wait() {
    asm volatile("cp.async.wait_group %0;" :: "n"(N) : "memory");
}
#define LDSM4(R, A) \
    asm volatile("ldmatrix.sync.aligned.m8n8.x4.shared.b16 {%0,%1,%2,%3}, [%4];" \
        : "=r"((R)[0]), "=r"((R)[1]), "=r"((R)[2]), "=r"((R)[3]) : "r"(A))
// int8 MMA: D(s32) += A(s8) * B(s8); K=32 per instruction
#define MMAS8(D, A, B0, B1) \
    asm volatile("mma.sync.aligned.m16n8k32.row.col.s32.s8.s8.s32 " \
        "{%0,%1,%2,%3},{%4,%5,%6,%7},{%8,%9},{%0,%1,%2,%3};" \
        : "+r"((D)[0]), "+r"((D)[1]), "+r"((D)[2]), "+r"((D)[3]) \
        : "r"((A)[0]), "r"((A)[1]), "r"((A)[2]), "r"((A)[3]), "r"(B0), "r"(B1))

// ------------------------------------------------------------------
// 1) per-tensor abs-mean: deterministic two-pass reduction (double)
// ------------------------------------------------------------------
__global__ void absmean_partial(const float4* __restrict__ w4, long long n4, int slot) {
    __shared__ double sd[256];
    double s = 0.0;
    long long i = (long long)blockIdx.x * 256 + threadIdx.x;
    const long long str = 512LL * 256;
    for (; i < n4; i += str) {
        float4 v = w4[i];
        s += (double)fabsf(v.x) + (double)fabsf(v.y) + (double)fabsf(v.z) + (double)fabsf(v.w);
    }
    sd[threadIdx.x] = s;
    __syncthreads();
    for (int o = 128; o > 0; o >>= 1) {
        if (threadIdx.x < o) sd[threadIdx.x] += sd[threadIdx.x + o];
        __syncthreads();
    }
    if (threadIdx.x == 0) g_part[slot * 512 + blockIdx.x] = sd[0];
}

// ------------------------------------------------------------------
// 2) ternary weight quantization -> int8 {-1,0,1}.
//    Scale folded in: each block re-sums g_part in the SAME order as
//    the old finalize kernel (bit-identical); block 0 publishes g_wdq.
// ------------------------------------------------------------------
__global__ void wquant(const float4* __restrict__ w4, long long n4, int slot, long long nelem) {
    __shared__ float ssc;
    if (threadIdx.x == 0) {
        double s0 = 0.0;
        for (int i = 0; i < 512; i++) s0 += g_part[slot * 512 + i];
        float m = fmaxf((float)(s0 / (double)nelem), 1e-5f);
        ssc = 1.0f / m;
        if (blockIdx.x == 0) g_wdq[slot] = m;
    }
    __syncthreads();
    int8_t* dst = (slot == 0) ? g_wqg : g_wqd;
    const float s = ssc;
    long long i = (long long)blockIdx.x * 256 + threadIdx.x;
    const long long str = 1024LL * 256;
    for (; i < n4; i += str) {
        float4 v = w4[i];
        int q0 = (int)fminf(1.f, fmaxf(-1.f, rintf(v.x * s)));
        int q1 = (int)fminf(1.f, fmaxf(-1.f, rintf(v.y * s)));
        int q2 = (int)fminf(1.f, fmaxf(-1.f, rintf(v.z * s)));
        int q3 = (int)fminf(1.f, fmaxf(-1.f, rintf(v.w * s)));
        uint32_t p = (uint32_t)(q0 & 0xff) | ((uint32_t)(q1 & 0xff) << 8) |
                     ((uint32_t)(q2 & 0xff) << 16) | ((uint32_t)(q3 & 0xff) << 24);
        reinterpret_cast<uint32_t*>(dst)[i] = p;
    }
}

// ------------------------------------------------------------------
// 3) per-token RMSNorm + int8 absmax fake-quant -> int8 codes.
//    Row cached in dynamic SMEM; float math BIT-IDENTICAL.
// ------------------------------------------------------------------
__global__ void act_quant(const float* __restrict__ xin, const float* __restrict__ g,
                          int which, int Dlen) {
    extern __shared__ float srow[];
    __shared__ float red[256];
    __shared__ float bc[2];
    const int tok = blockIdx.x;
    const float* xrow = (which == 1 ? xin : g_swi) + (size_t)tok * Dlen;
    const float4* x4 = reinterpret_cast<const float4*>(xrow);
    const float4* g4 = reinterpret_cast<const float4*>(g);
    float4* s4 = reinterpret_cast<float4*>(srow);
    const int n4 = Dlen >> 2;
    const int tid = threadIdx.x;

    float ss = 0.f, am = 0.f;
    for (int i = tid; i < n4; i += 256) {
        float4 v = x4[i];
        float4 gv = g4[i];
        s4[i] = v;
        ss = fmaf(v.x, v.x, ss); ss = fmaf(v.y, v.y, ss);
        ss = fmaf(v.z, v.z, ss); ss = fmaf(v.w, v.w, ss);
        am = fmaxf(am, fmaxf(fmaxf(fabsf(v.x * gv.x), fabsf(v.y * gv.y)),
                             fmaxf(fabsf(v.z * gv.z), fabsf(v.w * gv.w))));
    }
    red[tid] = ss; __syncthreads();
    for (int o = 128; o > 0; o >>= 1) { if (tid < o) red[tid] += red[tid + o]; __syncthreads(); }
    float sumsq = red[0]; __syncthreads();
    red[tid] = am; __syncthreads();
    for (int o = 128; o > 0; o >>= 1) { if (tid < o) red[tid] = fmaxf(red[tid], red[tid + o]); __syncthreads(); }
    if (tid == 0) {
        float rstd = 1.0f / sqrtf(sumsq / (float)Dlen + 1e-6f);
        float axn = red[0] * rstd;
        float cm = fmaxf(axn, 1e-5f);
        bc[0] = rstd; bc[1] = 127.0f / cm;
        (which == 1 ? g_isx1 : g_isx2)[tok] = cm / 127.0f;
    }
    __syncthreads();
    const float rstd = bc[0], sc = bc[1];
    int8_t* orow = (which == 1 ? g_xq1 : g_xq2) + (size_t)tok * Dlen;
    for (int i = tid; i < n4; i += 256) {
        float4 v = s4[i];
        float4 gv = g4[i];
        int q0 = (int)fminf(127.f, fmaxf(-128.f, rintf(v.x * rstd * gv.x * sc)));
        int q1 = (int)fminf(127.f, fmaxf(-128.f, rintf(v.y * rstd * gv.y * sc)));
        int q2 = (int)fminf(127.f, fmaxf(-128.f, rintf(v.z * rstd * gv.z * sc)));
        int q3 = (int)fminf(127.f, fmaxf(-128.f, rintf(v.w * rstd * gv.w * sc)));
        uint32_t p = (uint32_t)(q0 & 0xff) | ((uint32_t)(q1 & 0xff) << 8) |
                     ((uint32_t)(q2 & 0xff) << 16) | ((uint32_t)(q3 & 0xff) << 24);
        reinterpret_cast<uint32_t*>(orow)[i] = p;
    }
}

// ------------------------------------------------------------------
// 4) int8 IMMA GEMM, generic tile:
//    MW warps in M (tileM=MW*32), 2 warps in N (tileN=TN), MW*64 thr.
//    NB==2 (GEMM1): MW=4, TN=64, S=3, OCC=2 -> 2 CTAs/SM, 16 warps/SM.
//    NB==1 (GEMM2): MW=4, TN=64, S=3, OCC=3 -> 3 CTAs/SM, 24 warps/SM.
//    K-chunk 128 int8, SW128 XOR swizzle, single-barrier pipeline.
// ------------------------------------------------------------------
template<int NB, int S, int MW, int TN, int OCC>
__global__ void __launch_bounds__(MW * 64, OCC) gemm_mma(float* __restrict__ out) {
    constexpr int TM     = MW * 32;
    constexpr int NTHR   = MW * 64;
    constexpr int WN     = TN / 2;                        // warp N extent
    constexpr int NJ     = WN / 16;                       // 16-col groups/warp
    constexpr int ABYTES = TM * 128;
    constexpr int BBYTES = TN * 128;
    constexpr int STAGE  = ABYTES + NB * BBYTES;
    constexpr int RPR    = NTHR / 8;                      // rows per cp16 round
    constexpr int AR     = TM / RPR;
    constexpr int BR     = TN / RPR;
    const int Kdim = (NB == 2) ? DDIM : IDIM;
    const int nk = Kdim / 128;
    const int8_t* A = (NB == 2) ? g_xq1 : g_xq2;
    const int8_t* B = (NB == 2) ? g_wqg : g_wqd;
    const float* invs = (NB == 2) ? g_isx1 : g_isx2;
    const int outStride = (NB == 2) ? IDIM : DDIM;
    float* outp = (NB == 2) ? g_swi : out;

    extern __shared__ char dsm[];
    uint32_t dynbase = smem_u32(dsm);
    dynbase = (dynbase + 1023u) & ~1023u;

    const int tid = threadIdx.x;
    const int wid = tid >> 5, lid = tid & 31;
    const int wm = wid % MW, wn = wid / MW;
    const int m0 = blockIdx.y * TM, n0 = blockIdx.x * TN;

    const int c = tid & 7;
    const int r0 = tid >> 3;                              // 0 .. RPR-1
    const uint32_t dOff = (uint32_t)r0 * 128 + (uint32_t)((c * 16) ^ ((r0 & 7) << 4));
    const size_t rowstep = (size_t)RPR * Kdim;
    const int8_t* baseA  = A + (size_t)(m0 + r0) * Kdim + c * 16;
    const int8_t* baseB0 = B + (size_t)(n0 + r0) * Kdim + c * 16;
    const int8_t* baseB1 = B + (size_t)(IDIM + n0 + r0) * Kdim + c * 16;

    auto load_stage = [&](int s, int kc) {
        const uint32_t st = dynbase + (uint32_t)s * STAGE;
        const size_t ko = (size_t)kc * 128;
#pragma unroll
        for (int i = 0; i < AR; i++) cp16(st + dOff + i * (RPR * 128), baseA + i * rowstep + ko);
#pragma unroll
        for (int i = 0; i < BR; i++) cp16(st + ABYTES + dOff + i * (RPR * 128), baseB0 + i * rowstep + ko);
        if (NB == 2) {
#pragma unroll
            for (int i = 0; i < BR; i++) cp16(st + ABYTES + BBYTES + dOff + i * (RPR * 128), baseB1 + i * rowstep + ko);
        }
    };

    const int rla = (lid & 7) + ((lid >> 3) & 1) * 8;
    const uint32_t xorv = (uint32_t)(lid & 7) << 4;
    const uint32_t colsel = (uint32_t)(lid >> 4) * 16;

    int32_t accg[2][2 * NJ][4];
    int32_t accv[(NB == 2) ? 2 : 1][2 * NJ][4];
#pragma unroll
    for (int i = 0; i < 2; i++)
#pragma unroll
        for (int j = 0; j < 2 * NJ; j++)
#pragma unroll
            for (int u = 0; u < 4; u++) { accg[i][j][u] = 0; if (NB == 2) accv[i][j][u] = 0; }

#pragma unroll
    for (int k = 0; k < S - 1; ++k) { load_stage(k, k); cp_commit(); }

#pragma unroll 1
    for (int k = 0; k < nk; ++k) {
        cp_wait<S - 2>();
        __syncthreads();
        if (k + S - 1 < nk) load_stage((k + S - 1) % S, k + S - 1);
        cp_commit();

        const uint32_t stA = dynbase + (uint32_t)(k % S) * STAGE;
#pragma unroll
        for (int ks = 0; ks < 4; ++ks) {
            const uint32_t kcol = ((uint32_t)(ks * 32) + colsel) ^ xorv;
            uint32_t a[2][4];
#pragma unroll
            for (int i = 0; i < 2; ++i)
                LDSM4(a[i], stA + (uint32_t)((wm * 32 + i * 16 + rla) * 128) + kcol);
#pragma unroll
            for (int j = 0; j < NJ; ++j) {
                uint32_t bg[4];
                LDSM4(bg, stA + (uint32_t)ABYTES + (uint32_t)((wn * WN + j * 16 + rla) * 128) + kcol);
#pragma unroll
                for (int i = 0; i < 2; ++i) {
                    MMAS8(accg[i][j * 2],     a[i], bg[0], bg[2]);
                    MMAS8(accg[i][j * 2 + 1], a[i], bg[1], bg[3]);
                }
                if (NB == 2) {
                    uint32_t bv[4];
                    LDSM4(bv, stA + (uint32_t)(ABYTES + BBYTES) + (uint32_t)((wn * WN + j * 16 + rla) * 128) + kcol);
#pragma unroll
                    for (int i = 0; i < 2; ++i) {
                        MMAS8(accv[i][j * 2],     a[i], bv[0], bv[2]);
                        MMAS8(accv[i][j * 2 + 1], a[i], bv[1], bv[3]);
                    }
                }
            }
        }
    }

    const float wdq = g_wdq[(NB == 2) ? 0 : 1];
#pragma unroll
    for (int i = 0; i < 2; ++i) {
        const int r1 = m0 + wm * 32 + i * 16 + (lid >> 2);
        const int r2 = r1 + 8;
        const float s1 = invs[r1] * wdq;
        const float s2 = invs[r2] * wdq;
        float* row1 = outp + (size_t)r1 * outStride + n0 + wn * WN + (lid & 3) * 2;
        float* row2 = outp + (size_t)r2 * outStride + n0 + wn * WN + (lid & 3) * 2;
#pragma unroll
        for (int j = 0; j < 2 * NJ; ++j) {
            float2 o1, o2;
            if (NB == 2) {
                float gt0 = (float)accg[i][j][0] * s1, vv0 = (float)accv[i][j][0] * s1;
                float gt1 = (float)accg[i][j][1] * s1, vv1 = (float)accv[i][j][1] * s1;
                float gt2 = (float)accg[i][j][2] * s2, vv2 = (float)accv[i][j][2] * s2;
                float gt3 = (float)accg[i][j][3] * s2, vv3 = (float)accv[i][j][3] * s2;
                o1.x = gt0 / (1.f + expf(-gt0)) * vv0;
                o1.y = gt1 / (1.f + expf(-gt1)) * vv1;
                o2.x = gt2 / (1.f + expf(-gt2)) * vv2;
                o2.y = gt3 / (1.f + expf(-gt3)) * vv3;
            } else {
                o1.x = (float)accg[i][j][0] * s1; o1.y = (float)accg[i][j][1] * s1;
                o2.x = (float)accg[i][j][2] * s2; o2.y = (float)accg[i][j][3] * s2;
            }
            *reinterpret_cast<float2*>(row1 + j * 8) = o1;
            *reinterpret_cast<float2*>(row2 + j * 8) = o2;
        }
    }
}

// ------------------------------------------------------------------
// launch — order keeps GEMM1 at index 3 for ncu sampling:
//   0 absmean_g, 1 actq1, 2 wquant_g, 3 GEMM1, 4 actq2,
//   5 absmean_d, 6 wquant_d, 7 GEMM2
// ------------------------------------------------------------------
extern "C" void kernel_launch(void* const* d_in, const int* in_sizes, int n_in,
                              void* d_out, int out_size) {
    const float* x      = (const float*)d_in[0];
    const float* w_gate = (const float*)d_in[1];
    const float* g_gate = (const float*)d_in[2];
    const float* w_down = (const float*)d_in[3];
    const float* g_down = (const float*)d_in[4];
    float* out = (float*)d_out;

    const int smem1 = 3 * (128 * 128 + 2 * 64 * 128) + 1024;   // 99328
    const int smem2 = 3 * (128 * 128 + 64 * 128) + 1024;       // 74752
    cudaFuncSetAttribute((const void*)gemm_mma<2, 3, 4, 64, 2>, cudaFuncAttributeMaxDynamicSharedMemorySize, smem1);
    cudaFuncSetAttribute((const void*)gemm_mma<1, 3, 4, 64, 3>, cudaFuncAttributeMaxDynamicSharedMemorySize, smem2);

    absmean_partial<<<512, 256>>>((const float4*)w_gate, (long long)NGATE * DDIM / 4, 0);
    act_quant<<<TOKENS, 256, DDIM * 4>>>(x, g_gate, 1, DDIM);
    wquant<<<1024, 256>>>((const float4*)w_gate, (long long)NGATE * DDIM / 4, 0, (long long)NGATE * DDIM);
    gemm_mma<2, 3, 4, 64, 2><<<dim3(IDIM / 64, TOKENS / 128), 256, smem1>>>(nullptr);
    act_quant<<<TOKENS, 256, IDIM * 4>>>(nullptr, g_down, 2, IDIM);
    absmean_partial<<<512, 256>>>((const float4*)w_down, (long long)DDIM * IDIM / 4, 1);
    wquant<<<1024, 256>>>((const float4*)w_down, (long long)DDIM * IDIM / 4, 1, (long long)DDIM * IDIM);
    gemm_mma<1, 3, 4, 64, 3><<<dim3(DDIM / 64, TOKENS / 128), 256, smem2>>>(out);
}

// round 17
// speedup vs baseline: 1.0336x; 1.0336x over previous
// v16 — GEMM2 reverted to best cfg <1,3,4,128,2>; weight-prep on a side
//        stream overlapped with the activation chain (capture-safe events).
#include <cuda_runtime.h>
#include <cuda_bf16.h>
#include <cstdint>
#include <cstddef>

#define TOKENS 16384
#define DDIM   2048
#define IDIM   5632
#define NGATE  (2*IDIM)

// ------------------------------------------------------------------
// Device-global scratch (module-load allocation; no runtime allocs)
// ------------------------------------------------------------------
__device__ int8_t g_xq1[(size_t)TOKENS * DDIM];   // quantized x (int8 codes)
__device__ float  g_isx1[TOKENS];                 // per-token dequant scale (absmax/127)
__device__ int8_t g_wqg[(size_t)NGATE * DDIM];    // ternary w_gate (int8)
__device__ int8_t g_wqd[(size_t)DDIM * IDIM];     // ternary w_down (int8)
__device__ float  g_swi[(size_t)TOKENS * IDIM];   // swiglu intermediate (fp32)
__device__ int8_t g_xq2[(size_t)TOKENS * IDIM];   // quantized swiglu (int8 codes)
__device__ float  g_isx2[TOKENS];
__device__ double g_part[1024];                   // reduction partials
__device__ float  g_wdq[2];                       // weight dequant factors (mean)

// ------------------------------------------------------------------
// PTX helpers (sm_100-baseline: cp.async / ldmatrix / mma.sync s8)
// ------------------------------------------------------------------
__device__ __forceinline__ uint32_t smem_u32(const void* p) {
    uint32_t a;
    asm("{ .reg .u64 t; cvta.to.shared.u64 t, %1; cvt.u32.u64 %0, t; }" : "=r"(a) : "l"(p));
    return a;
}
__device__ __forceinline__ void cp16(uint32_t dst, const void* src) {
    asm volatile("cp.async.cg.shared.global [%0], [%1], 16;" :: "r"(dst), "l"(src) : "memory");
}
__device__ __forceinline__ void cp_commit() {
    asm volatile("cp.async.commit_group;" ::: "memory");
}
template<int N> __device__ __forceinline__ void cp_wait() {
    asm volatile("cp.async.wait_group %0;" :: "n"(N) : "memory");
}
#define LDSM4(R, A) \
    asm volatile("ldmatrix.sync.aligned.m8n8.x4.shared.b16 {%0,%1,%2,%3}, [%4];" \
        : "=r"((R)[0]), "=r"((R)[1]), "=r"((R)[2]), "=r"((R)[3]) : "r"(A))
// int8 MMA: D(s32) += A(s8) * B(s8); K=32 per instruction
#define MMAS8(D, A, B0, B1) \
    asm volatile("mma.sync.aligned.m16n8k32.row.col.s32.s8.s8.s32 " \
        "{%0,%1,%2,%3},{%4,%5,%6,%7},{%8,%9},{%0,%1,%2,%3};" \
        : "+r"((D)[0]), "+r"((D)[1]), "+r"((D)[2]), "+r"((D)[3]) \
        : "r"((A)[0]), "r"((A)[1]), "r"((A)[2]), "r"((A)[3]), "r"(B0), "r"(B1))

// ------------------------------------------------------------------
// 1) per-tensor abs-mean: deterministic two-pass reduction (double)
// ------------------------------------------------------------------
__global__ void absmean_partial(const float4* __restrict__ w4, long long n4, int slot) {
    __shared__ double sd[256];
    double s = 0.0;
    long long i = (long long)blockIdx.x * 256 + threadIdx.x;
    const long long str = 512LL * 256;
    for (; i < n4; i += str) {
        float4 v = w4[i];
        s += (double)fabsf(v.x) + (double)fabsf(v.y) + (double)fabsf(v.z) + (double)fabsf(v.w);
    }
    sd[threadIdx.x] = s;
    __syncthreads();
    for (int o = 128; o > 0; o >>= 1) {
        if (threadIdx.x < o) sd[threadIdx.x] += sd[threadIdx.x + o];
        __syncthreads();
    }
    if (threadIdx.x == 0) g_part[slot * 512 + blockIdx.x] = sd[0];
}

// ------------------------------------------------------------------
// 2) ternary weight quantization -> int8 {-1,0,1}.
//    Scale folded in: each block re-sums g_part in the SAME order as
//    the old finalize kernel (bit-identical); block 0 publishes g_wdq.
// ------------------------------------------------------------------
__global__ void wquant(const float4* __restrict__ w4, long long n4, int slot, long long nelem) {
    __shared__ float ssc;
    if (threadIdx.x == 0) {
        double s0 = 0.0;
        for (int i = 0; i < 512; i++) s0 += g_part[slot * 512 + i];
        float m = fmaxf((float)(s0 / (double)nelem), 1e-5f);
        ssc = 1.0f / m;
        if (blockIdx.x == 0) g_wdq[slot] = m;
    }
    __syncthreads();
    int8_t* dst = (slot == 0) ? g_wqg : g_wqd;
    const float s = ssc;
    long long i = (long long)blockIdx.x * 256 + threadIdx.x;
    const long long str = 1024LL * 256;
    for (; i < n4; i += str) {
        float4 v = w4[i];
        int q0 = (int)fminf(1.f, fmaxf(-1.f, rintf(v.x * s)));
        int q1 = (int)fminf(1.f, fmaxf(-1.f, rintf(v.y * s)));
        int q2 = (int)fminf(1.f, fmaxf(-1.f, rintf(v.z * s)));
        int q3 = (int)fminf(1.f, fmaxf(-1.f, rintf(v.w * s)));
        uint32_t p = (uint32_t)(q0 & 0xff) | ((uint32_t)(q1 & 0xff) << 8) |
                     ((uint32_t)(q2 & 0xff) << 16) | ((uint32_t)(q3 & 0xff) << 24);
        reinterpret_cast<uint32_t*>(dst)[i] = p;
    }
}

// ------------------------------------------------------------------
// 3) per-token RMSNorm + int8 absmax fake-quant -> int8 codes.
//    Row cached in dynamic SMEM; float math BIT-IDENTICAL.
// ------------------------------------------------------------------
__global__ void act_quant(const float* __restrict__ xin, const float* __restrict__ g,
                          int which, int Dlen) {
    extern __shared__ float srow[];
    __shared__ float red[256];
    __shared__ float bc[2];
    const int tok = blockIdx.x;
    const float* xrow = (which == 1 ? xin : g_swi) + (size_t)tok * Dlen;
    const float4* x4 = reinterpret_cast<const float4*>(xrow);
    const float4* g4 = reinterpret_cast<const float4*>(g);
    float4* s4 = reinterpret_cast<float4*>(srow);
    const int n4 = Dlen >> 2;
    const int tid = threadIdx.x;

    float ss = 0.f, am = 0.f;
    for (int i = tid; i < n4; i += 256) {
        float4 v = x4[i];
        float4 gv = g4[i];
        s4[i] = v;
        ss = fmaf(v.x, v.x, ss); ss = fmaf(v.y, v.y, ss);
        ss = fmaf(v.z, v.z, ss); ss = fmaf(v.w, v.w, ss);
        am = fmaxf(am, fmaxf(fmaxf(fabsf(v.x * gv.x), fabsf(v.y * gv.y)),
                             fmaxf(fabsf(v.z * gv.z), fabsf(v.w * gv.w))));
    }
    red[tid] = ss; __syncthreads();
    for (int o = 128; o > 0; o >>= 1) { if (tid < o) red[tid] += red[tid + o]; __syncthreads(); }
    float sumsq = red[0]; __syncthreads();
    red[tid] = am; __syncthreads();
    for (int o = 128; o > 0; o >>= 1) { if (tid < o) red[tid] = fmaxf(red[tid], red[tid + o]); __syncthreads(); }
    if (tid == 0) {
        float rstd = 1.0f / sqrtf(sumsq / (float)Dlen + 1e-6f);
        float axn = red[0] * rstd;
        float cm = fmaxf(axn, 1e-5f);
        bc[0] = rstd; bc[1] = 127.0f / cm;
        (which == 1 ? g_isx1 : g_isx2)[tok] = cm / 127.0f;
    }
    __syncthreads();
    const float rstd = bc[0], sc = bc[1];
    int8_t* orow = (which == 1 ? g_xq1 : g_xq2) + (size_t)tok * Dlen;
    for (int i = tid; i < n4; i += 256) {
        float4 v = s4[i];
        float4 gv = g4[i];
        int q0 = (int)fminf(127.f, fmaxf(-128.f, rintf(v.x * rstd * gv.x * sc)));
        int q1 = (int)fminf(127.f, fmaxf(-128.f, rintf(v.y * rstd * gv.y * sc)));
        int q2 = (int)fminf(127.f, fmaxf(-128.f, rintf(v.z * rstd * gv.z * sc)));
        int q3 = (int)fminf(127.f, fmaxf(-128.f, rintf(v.w * rstd * gv.w * sc)));
        uint32_t p = (uint32_t)(q0 & 0xff) | ((uint32_t)(q1 & 0xff) << 8) |
                     ((uint32_t)(q2 & 0xff) << 16) | ((uint32_t)(q3 & 0xff) << 24);
        reinterpret_cast<uint32_t*>(orow)[i] = p;
    }
}

// ------------------------------------------------------------------
// 4) int8 IMMA GEMM, generic tile:
//    MW warps in M (tileM=MW*32), 2 warps in N (tileN=TN), MW*64 thr.
//    NB==2 (GEMM1): MW=4, TN=64,  S=3, OCC=2 -> 2 CTAs/SM, 16 warps/SM.
//    NB==1 (GEMM2): MW=4, TN=128, S=3, OCC=2 -> 2 CTAs/SM, 16 warps/SM.
//    K-chunk 128 int8, SW128 XOR swizzle, single-barrier pipeline.
// ------------------------------------------------------------------
template<int NB, int S, int MW, int TN, int OCC>
__global__ void __launch_bounds__(MW * 64, OCC) gemm_mma(float* __restrict__ out) {
    constexpr int TM     = MW * 32;
    constexpr int NTHR   = MW * 64;
    constexpr int WN     = TN / 2;                        // warp N extent
    constexpr int NJ     = WN / 16;                       // 16-col groups/warp
    constexpr int ABYTES = TM * 128;
    constexpr int BBYTES = TN * 128;
    constexpr int STAGE  = ABYTES + NB * BBYTES;
    constexpr int RPR    = NTHR / 8;                      // rows per cp16 round
    constexpr int AR     = TM / RPR;
    constexpr int BR     = TN / RPR;
    const int Kdim = (NB == 2) ? DDIM : IDIM;
    const int nk = Kdim / 128;
    const int8_t* A = (NB == 2) ? g_xq1 : g_xq2;
    const int8_t* B = (NB == 2) ? g_wqg : g_wqd;
    const float* invs = (NB == 2) ? g_isx1 : g_isx2;
    const int outStride = (NB == 2) ? IDIM : DDIM;
    float* outp = (NB == 2) ? g_swi : out;

    extern __shared__ char dsm[];
    uint32_t dynbase = smem_u32(dsm);
    dynbase = (dynbase + 1023u) & ~1023u;

    const int tid = threadIdx.x;
    const int wid = tid >> 5, lid = tid & 31;
    const int wm = wid % MW, wn = wid / MW;
    const int m0 = blockIdx.y * TM, n0 = blockIdx.x * TN;

    const int c = tid & 7;
    const int r0 = tid >> 3;                              // 0 .. RPR-1
    const uint32_t dOff = (uint32_t)r0 * 128 + (uint32_t)((c * 16) ^ ((r0 & 7) << 4));
    const size_t rowstep = (size_t)RPR * Kdim;
    const int8_t* baseA  = A + (size_t)(m0 + r0) * Kdim + c * 16;
    const int8_t* baseB0 = B + (size_t)(n0 + r0) * Kdim + c * 16;
    const int8_t* baseB1 = B + (size_t)(IDIM + n0 + r0) * Kdim + c * 16;

    auto load_stage = [&](int s, int kc) {
        const uint32_t st = dynbase + (uint32_t)s * STAGE;
        const size_t ko = (size_t)kc * 128;
#pragma unroll
        for (int i = 0; i < AR; i++) cp16(st + dOff + i * (RPR * 128), baseA + i * rowstep + ko);
#pragma unroll
        for (int i = 0; i < BR; i++) cp16(st + ABYTES + dOff + i * (RPR * 128), baseB0 + i * rowstep + ko);
        if (NB == 2) {
#pragma unroll
            for (int i = 0; i < BR; i++) cp16(st + ABYTES + BBYTES + dOff + i * (RPR * 128), baseB1 + i * rowstep + ko);
        }
    };

    const int rla = (lid & 7) + ((lid >> 3) & 1) * 8;
    const uint32_t xorv = (uint32_t)(lid & 7) << 4;
    const uint32_t colsel = (uint32_t)(lid >> 4) * 16;

    int32_t accg[2][2 * NJ][4];
    int32_t accv[(NB == 2) ? 2 : 1][2 * NJ][4];
#pragma unroll
    for (int i = 0; i < 2; i++)
#pragma unroll
        for (int j = 0; j < 2 * NJ; j++)
#pragma unroll
            for (int u = 0; u < 4; u++) { accg[i][j][u] = 0; if (NB == 2) accv[i][j][u] = 0; }

#pragma unroll
    for (int k = 0; k < S - 1; ++k) { load_stage(k, k); cp_commit(); }

#pragma unroll 1
    for (int k = 0; k < nk; ++k) {
        cp_wait<S - 2>();
        __syncthreads();
        if (k + S - 1 < nk) load_stage((k + S - 1) % S, k + S - 1);
        cp_commit();

        const uint32_t stA = dynbase + (uint32_t)(k % S) * STAGE;
#pragma unroll
        for (int ks = 0; ks < 4; ++ks) {
            const uint32_t kcol = ((uint32_t)(ks * 32) + colsel) ^ xorv;
            uint32_t a[2][4];
#pragma unroll
            for (int i = 0; i < 2; ++i)
                LDSM4(a[i], stA + (uint32_t)((wm * 32 + i * 16 + rla) * 128) + kcol);
#pragma unroll
            for (int j = 0; j < NJ; ++j) {
                uint32_t bg[4];
                LDSM4(bg, stA + (uint32_t)ABYTES + (uint32_t)((wn * WN + j * 16 + rla) * 128) + kcol);
#pragma unroll
                for (int i = 0; i < 2; ++i) {
                    MMAS8(accg[i][j * 2],     a[i], bg[0], bg[2]);
                    MMAS8(accg[i][j * 2 + 1], a[i], bg[1], bg[3]);
                }
                if (NB == 2) {
                    uint32_t bv[4];
                    LDSM4(bv, stA + (uint32_t)(ABYTES + BBYTES) + (uint32_t)((wn * WN + j * 16 + rla) * 128) + kcol);
#pragma unroll
                    for (int i = 0; i < 2; ++i) {
                        MMAS8(accv[i][j * 2],     a[i], bv[0], bv[2]);
                        MMAS8(accv[i][j * 2 + 1], a[i], bv[1], bv[3]);
                    }
                }
            }
        }
    }

    const float wdq = g_wdq[(NB == 2) ? 0 : 1];
#pragma unroll
    for (int i = 0; i < 2; ++i) {
        const int r1 = m0 + wm * 32 + i * 16 + (lid >> 2);
        const int r2 = r1 + 8;
        const float s1 = invs[r1] * wdq;
        const float s2 = invs[r2] * wdq;
        float* row1 = outp + (size_t)r1 * outStride + n0 + wn * WN + (lid & 3) * 2;
        float* row2 = outp + (size_t)r2 * outStride + n0 + wn * WN + (lid & 3) * 2;
#pragma unroll
        for (int j = 0; j < 2 * NJ; ++j) {
            float2 o1, o2;
            if (NB == 2) {
                float gt0 = (float)accg[i][j][0] * s1, vv0 = (float)accv[i][j][0] * s1;
                float gt1 = (float)accg[i][j][1] * s1, vv1 = (float)accv[i][j][1] * s1;
                float gt2 = (float)accg[i][j][2] * s2, vv2 = (float)accv[i][j][2] * s2;
                float gt3 = (float)accg[i][j][3] * s2, vv3 = (float)accv[i][j][3] * s2;
                o1.x = gt0 / (1.f + expf(-gt0)) * vv0;
                o1.y = gt1 / (1.f + expf(-gt1)) * vv1;
                o2.x = gt2 / (1.f + expf(-gt2)) * vv2;
                o2.y = gt3 / (1.f + expf(-gt3)) * vv3;
            } else {
                o1.x = (float)accg[i][j][0] * s1; o1.y = (float)accg[i][j][1] * s1;
                o2.x = (float)accg[i][j][2] * s2; o2.y = (float)accg[i][j][3] * s2;
            }
            *reinterpret_cast<float2*>(row1 + j * 8) = o1;
            *reinterpret_cast<float2*>(row2 + j * 8) = o2;
        }
    }
}

// ------------------------------------------------------------------
// launch — weight-prep on side stream sW, overlapped with the
// activation chain on the main (capture-origin) stream:
//   main: actq1 ──────────── GEMM1 ── actq2 ── GEMM2
//   sW:   absmean_g→wquant_g ─┘(evWg)  absmean_d→wquant_d ─┘(evWd)
// ------------------------------------------------------------------
extern "C" void kernel_launch(void* const* d_in, const int* in_sizes, int n_in,
                              void* d_out, int out_size) {
    const float* x      = (const float*)d_in[0];
    const float* w_gate = (const float*)d_in[1];
    const float* g_gate = (const float*)d_in[2];
    const float* w_down = (const float*)d_in[3];
    const float* g_down = (const float*)d_in[4];
    float* out = (float*)d_out;

    const int smem1 = 3 * (128 * 128 + 2 * 64 * 128) + 1024;   // 99328
    const int smem2 = 3 * (128 * 128 + 128 * 128) + 1024;      // 99328
    cudaFuncSetAttribute((const void*)gemm_mma<2, 3, 4, 64, 2>, cudaFuncAttributeMaxDynamicSharedMemorySize, smem1);
    cudaFuncSetAttribute((const void*)gemm_mma<1, 3, 4, 128, 2>, cudaFuncAttributeMaxDynamicSharedMemorySize, smem2);

    // Side stream + events, created fresh per call (kernel_launch runs only a
    // handful of times: correctness + capture; replays use the graph).
    cudaStream_t sW;
    cudaEvent_t evFork, evWg, evWd;
    cudaStreamCreateWithFlags(&sW, cudaStreamNonBlocking);
    cudaEventCreateWithFlags(&evFork, cudaEventDisableTiming);
    cudaEventCreateWithFlags(&evWg, cudaEventDisableTiming);
    cudaEventCreateWithFlags(&evWd, cudaEventDisableTiming);

    // Fork side stream off the capture-origin stream.
    cudaEventRecord(evFork, 0);
    cudaStreamWaitEvent(sW, evFork, 0);

    // Weight-prep chain on sW.
    absmean_partial<<<512, 256, 0, sW>>>((const float4*)w_gate, (long long)NGATE * DDIM / 4, 0);
    wquant<<<1024, 256, 0, sW>>>((const float4*)w_gate, (long long)NGATE * DDIM / 4, 0, (long long)NGATE * DDIM);
    cudaEventRecord(evWg, sW);
    absmean_partial<<<512, 256, 0, sW>>>((const float4*)w_down, (long long)DDIM * IDIM / 4, 1);
    wquant<<<1024, 256, 0, sW>>>((const float4*)w_down, (long long)DDIM * IDIM / 4, 1, (long long)DDIM * IDIM);
    cudaEventRecord(evWd, sW);

    // Activation chain on the main stream.
    act_quant<<<TOKENS, 256, DDIM * 4>>>(x, g_gate, 1, DDIM);
    cudaStreamWaitEvent(0, evWg, 0);
    gemm_mma<2, 3, 4, 64, 2><<<dim3(IDIM / 64, TOKENS / 128), 256, smem1>>>(nullptr);
    act_quant<<<TOKENS, 256, IDIM * 4>>>(nullptr, g_down, 2, IDIM);
    cudaStreamWaitEvent(0, evWd, 0);
    gemm_mma<1, 3, 4, 128, 2><<<dim3(DDIM / 128, TOKENS / 128), 256, smem2>>>(out);
}